// round 11
// baseline (speedup 1.0000x reference)
#include <cuda_runtime.h>
#include <cstdint>
#include <math.h>

#define B_DIM   16384
#define IN_DIM  784
#define H_DIM   4096
#define OUT_DIM 10
#define KPAD    832            // 784 padded to 13*64
#define NCHUNK  13             // K chunks of 64
#define MT      64
#define NT      128
#define NSLOT   6              // chunk-slot ring
#define MTILES  (B_DIM / MT)   // 256

// chunk slot: A limbs [3][64 rows][80B] + B [128 rows][80B]
#define A_ROWB      80
#define A_LIMB_B    (64 * A_ROWB)            // 5120
#define STAGE_A_B   (3 * A_LIMB_B)           // 15360
#define STAGE_B_B   (128 * A_ROWB)           // 10240
#define STAGE_BYTES (STAGE_A_B + STAGE_B_B)  // 25600
#define SMEM_TOTAL  (NSLOT * STAGE_BYTES)    // 153600

// ---------------- scratch ----------------
__device__ __align__(1024) int8_t g_Aq[(size_t)B_DIM * 3 * KPAD];   // 40.9 MB
__device__ __align__(1024) int8_t g_Bs[(size_t)H_DIM * KPAD];       // 3.4 MB
__device__ __align__(1024) float  g_h[(size_t)B_DIM * H_DIM];       // 268 MB
__device__ float    g_psum[MTILES * H_DIM];
__device__ float    g_psq [MTILES * H_DIM];
__device__ float    g_thr [H_DIM];
__device__ unsigned g_negw[H_DIM / 32];
__device__ unsigned g_w2b [OUT_DIM * (H_DIM / 32)];

// ---------------- helpers ----------------
__device__ __forceinline__ uint32_t smem_u32(const void* p) {
    uint32_t a;
    asm("{ .reg .u64 t; cvta.to.shared.u64 t, %1; cvt.u32.u64 %0, t; }" : "=r"(a) : "l"(p));
    return a;
}
__device__ __forceinline__ void cp_async16(uint32_t dst, const void* src) {
    asm volatile("cp.async.cg.shared.global [%0], [%1], 16;" :: "r"(dst), "l"(src) : "memory");
}
__device__ __forceinline__ void cp_commit() {
    asm volatile("cp.async.commit_group;" ::: "memory");
}
__device__ __forceinline__ void ldsm4(uint32_t addr, uint32_t* r) {
    asm volatile("ldmatrix.sync.aligned.m8n8.x4.shared.b16 {%0,%1,%2,%3}, [%4];"
                 : "=r"(r[0]), "=r"(r[1]), "=r"(r[2]), "=r"(r[3]) : "r"(addr));
}
__device__ __forceinline__ void imma(int* d, const uint32_t* a, const uint32_t* b) {
    asm volatile(
        "mma.sync.aligned.m16n8k32.row.col.s32.s8.s8.s32 "
        "{%0,%1,%2,%3}, {%4,%5,%6,%7}, {%8,%9}, {%0,%1,%2,%3};"
        : "+r"(d[0]), "+r"(d[1]), "+r"(d[2]), "+r"(d[3])
        : "r"(a[0]), "r"(a[1]), "r"(a[2]), "r"(a[3]), "r"(b[0]), "r"(b[1]));
}

// one chunk of MMAs with next chunk's fragment loads interleaved behind them
__device__ __forceinline__ void chunk_body(
    uint32_t sb, uint32_t aWarp, uint32_t bWarp,
    int d[3][4][4], uint32_t afr[3][2][4],
    uint32_t (*bcur)[4], uint32_t (*bnxt)[4],
    int nslot, bool load)
{
    const uint32_t sAn = sb + (uint32_t)(nslot * STAGE_BYTES);
    const uint32_t sBn = sAn + STAGE_A_B;
    if (load) {
        #pragma unroll
        for (int nb = 0; nb < 4; nb++)
            ldsm4(sBn + bWarp + (uint32_t)(nb * 8 * A_ROWB), bnxt[nb]);
    }
    #pragma unroll
    for (int l = 0; l < 3; l++) {
        #pragma unroll
        for (int ks = 0; ks < 2; ks++)
            #pragma unroll
            for (int nb = 0; nb < 4; nb++)
                imma(d[l][nb], afr[l][ks], &bcur[nb][ks * 2]);
        if (load) {
            #pragma unroll
            for (int ks = 0; ks < 2; ks++)
                ldsm4(sAn + l * A_LIMB_B + aWarp + (uint32_t)(ks * 32), afr[l][ks]);
        }
    }
}

// ---------------- prep: x -> 3 int8 limbs at scale 2^-20 ----------------
__global__ void k_prep_a(const float* __restrict__ x) {
    size_t i = (size_t)blockIdx.x * blockDim.x + threadIdx.x;
    if (i >= (size_t)B_DIM * (KPAD / 4)) return;
    int row = (int)(i / (KPAD / 4));
    int k4  = (int)(i % (KPAD / 4));
    int k   = k4 * 4;
    char4 l0 = make_char4(0, 0, 0, 0), l1 = l0, l2 = l0;
    if (k < IN_DIM) {
        float4 xv = *(const float4*)(x + (size_t)row * IN_DIM + k);
        float v[4] = {xv.x, xv.y, xv.z, xv.w};
        signed char a0[4], a1[4], a2[4];
        #pragma unroll
        for (int j = 0; j < 4; j++) {
            int q = __float2int_rn(v[j] * 1048576.0f);
            q = max(min(q, 8388607), -8388607);
            int b0 = (q << 24) >> 24;
            int q1 = (q - b0) >> 8;
            int b1 = (q1 << 24) >> 24;
            int b2 = (q1 - b1) >> 8;
            a0[j] = (signed char)b0; a1[j] = (signed char)b1; a2[j] = (signed char)b2;
        }
        l0 = make_char4(a0[0], a0[1], a0[2], a0[3]);
        l1 = make_char4(a1[0], a1[1], a1[2], a1[3]);
        l2 = make_char4(a2[0], a2[1], a2[2], a2[3]);
    }
    size_t base = (size_t)row * 3 * KPAD + k;
    *(char4*)(g_Aq + base)            = l0;
    *(char4*)(g_Aq + base + KPAD)     = l1;
    *(char4*)(g_Aq + base + 2 * KPAD) = l2;
}

__global__ void k_prep_w(const float* __restrict__ W1) {
    size_t i = (size_t)blockIdx.x * blockDim.x + threadIdx.x;
    if (i >= (size_t)H_DIM * (KPAD / 4)) return;
    int row = (int)(i / (KPAD / 4));
    int k4  = (int)(i % (KPAD / 4));
    int k   = k4 * 4;
    char4 s = make_char4(0, 0, 0, 0);
    if (k < IN_DIM) {
        float4 wv = *(const float4*)(W1 + (size_t)row * IN_DIM + k);
        float v[4] = {wv.x, wv.y, wv.z, wv.w};
        signed char sc[4];
        #pragma unroll
        for (int j = 0; j < 4; j++)
            sc[j] = (signed char)((v[j] > 0.f) ? 1 : ((v[j] < 0.f) ? -1 : 0));
        s = make_char4(sc[0], sc[1], sc[2], sc[3]);
    }
    *(char4*)(g_Bs + (size_t)row * KPAD + k) = s;
}

__global__ void k_prep_w2(const float* __restrict__ W2) {
    int idx = blockIdx.x * blockDim.x + threadIdx.x;
    if (idx >= OUT_DIM * 128) return;
    int o = idx / 128, w = idx % 128;
    unsigned bits = 0;
    for (int j = 0; j < 32; j++)
        if (W2[(size_t)o * H_DIM + w * 32 + j] > 0.f) bits |= (1u << j);
    g_w2b[idx] = bits;
}

// ---------------- GEMM1: 6-slot ring, one sync per chunk PAIR ----------------
__global__ void __launch_bounds__(512, 1) k_gemm1() {
    extern __shared__ __align__(128) char smem[];
    const uint32_t sb = smem_u32(smem);
    const int tid = threadIdx.x, lane = tid & 31, wid = tid >> 5;
    const int wm = wid & 3, wn = wid >> 2;       // 4 x 4 warp grid
    const int mbase = blockIdx.y * MT;
    const int nbase = blockIdx.x * NT;

    // cp.async granule plan: 1280 granules/chunk; threads<256 take 3, else 2
    const int ng = (tid < 256) ? 3 : 2;
    const int8_t* gsrc[3];
    uint32_t sdst[3];
    #pragma unroll
    for (int i = 0; i < 3; i++) {
        int g = tid + i * 512;
        if (g >= 1280) g = 0;   // dummy (unused when i >= ng)
        if (g < 768) {
            int limb = g >> 8, rem = g & 255, row = rem >> 2, c = rem & 3;
            gsrc[i] = g_Aq + ((size_t)(mbase + row) * 3 + limb) * KPAD + c * 16;
            sdst[i] = limb * A_LIMB_B + row * A_ROWB + c * 16;
        } else {
            int gb = g - 768, row = gb >> 2, c = gb & 3;
            gsrc[i] = g_Bs + (size_t)(nbase + row) * KPAD + c * 16;
            sdst[i] = STAGE_A_B + row * A_ROWB + c * 16;
        }
    }

    // ldmatrix lane offsets
    const int mi = lane >> 3, r8 = lane & 7;
    const uint32_t aLane = (uint32_t)(((mi & 1) * 8 + r8) * A_ROWB + (mi >> 1) * 16);
    const uint32_t bLane = (uint32_t)(r8 * A_ROWB + (mi & 1) * 16 + (mi >> 1) * 32);
    const uint32_t aWarp = (uint32_t)(wm * 16 * A_ROWB) + aLane;
    const uint32_t bWarp = (uint32_t)(wn * 32 * A_ROWB) + bLane;

    int d[3][4][4];
    #pragma unroll
    for (int l = 0; l < 3; l++)
        #pragma unroll
        for (int nb = 0; nb < 4; nb++)
            #pragma unroll
            for (int i = 0; i < 4; i++) d[l][nb][i] = 0;

    // prologue: prefetch chunks 0..5 into slots 0..5 (6 commit groups)
    #pragma unroll
    for (int s = 0; s < NSLOT; s++) {
        #pragma unroll
        for (int i = 0; i < 3; i++)
            if (i < ng) cp_async16(sb + s * STAGE_BYTES + sdst[i], gsrc[i] + s * 64);
        cp_commit();
    }

    uint32_t bfr[2][4][4];              // double-buffered B fragments
    uint32_t afr[3][2][4];              // A fragments, reloaded per-limb

    // wait for chunks 0,1; load chunk-0 fragments
    asm volatile("cp.async.wait_group 4;" ::: "memory");
    __syncthreads();
    {
        #pragma unroll
        for (int nb = 0; nb < 4; nb++)
            ldsm4(sb + STAGE_A_B + bWarp + (uint32_t)(nb * 8 * A_ROWB), bfr[0][nb]);
        #pragma unroll
        for (int l = 0; l < 3; l++)
            #pragma unroll
            for (int ks = 0; ks < 2; ks++)
                ldsm4(sb + l * A_LIMB_B + aWarp + (uint32_t)(ks * 32), afr[l][ks]);
    }

    int bi = 0;
    #pragma unroll
    for (int p = 0; p < 6; p++) {
        const int c0 = 2 * p;

        // first half: MMA chunk c0, load chunk c0+1 fragments (slot already visible)
        chunk_body(sb, aWarp, bWarp, d, afr, bfr[bi], bfr[bi ^ 1], (c0 + 1) % NSLOT, true);
        bi ^= 1;

        // one barrier per pair: make chunks c0+2, c0+3 visible
        if (p < 4)       asm volatile("cp.async.wait_group 2;" ::: "memory");
        else if (p == 4) asm volatile("cp.async.wait_group 1;" ::: "memory");
        else             asm volatile("cp.async.wait_group 0;" ::: "memory");
        __syncthreads();

        // prefetch chunks c0+6, c0+7 into the slots freed by chunks c0, c0+1
        if (c0 + 6 <= 12) {
            int s = (c0 + 6) % NSLOT;
            #pragma unroll
            for (int i = 0; i < 3; i++)
                if (i < ng) cp_async16(sb + s * STAGE_BYTES + sdst[i], gsrc[i] + (c0 + 6) * 64);
            cp_commit();
        }
        if (c0 + 7 <= 12) {
            int s = (c0 + 7) % NSLOT;
            #pragma unroll
            for (int i = 0; i < 3; i++)
                if (i < ng) cp_async16(sb + s * STAGE_BYTES + sdst[i], gsrc[i] + (c0 + 7) * 64);
            cp_commit();
        }

        // second half: MMA chunk c0+1, load chunk c0+2 fragments (just made visible)
        chunk_body(sb, aWarp, bWarp, d, afr, bfr[bi], bfr[bi ^ 1], (c0 + 2) % NSLOT, true);
        bi ^= 1;
    }
    // peeled chunk 12: fragments already in registers
    chunk_body(sb, aWarp, bWarp, d, afr, bfr[bi], bfr[bi ^ 1], 0, false);

    // ---- epilogue: h = (65536*S2 + 256*S1 + S0) * 2^-20 + fused column stats ----
    float s_loc[4][2], q_loc[4][2];
    #pragma unroll
    for (int nb = 0; nb < 4; nb++) { s_loc[nb][0] = s_loc[nb][1] = 0.f; q_loc[nb][0] = q_loc[nb][1] = 0.f; }

    {
        int row0 = mbase + wm * 16 + (lane >> 2);
        #pragma unroll
        for (int nb = 0; nb < 4; nb++) {
            int col = nbase + wn * 32 + nb * 8 + (lane & 3) * 2;
            float f[4];
            #pragma unroll
            for (int i = 0; i < 4; i++)
                f[i] = fmaf((float)d[2][nb][i], 65536.f,
                            fmaf((float)d[1][nb][i], 256.f,
                                 (float)d[0][nb][i])) * (1.f / 1048576.f);
            *(float2*)(g_h + (size_t)row0 * H_DIM + col)       = make_float2(f[0], f[1]);
            *(float2*)(g_h + (size_t)(row0 + 8) * H_DIM + col) = make_float2(f[2], f[3]);
            s_loc[nb][0] += f[0] + f[2];            q_loc[nb][0] += f[0] * f[0] + f[2] * f[2];
            s_loc[nb][1] += f[1] + f[3];            q_loc[nb][1] += f[1] * f[1] + f[3] * f[3];
        }
    }
    #pragma unroll
    for (int nb = 0; nb < 4; nb++)
        #pragma unroll
        for (int p = 0; p < 2; p++) {
            #pragma unroll
            for (int off = 4; off <= 16; off <<= 1) {
                s_loc[nb][p] += __shfl_xor_sync(0xFFFFFFFFu, s_loc[nb][p], off);
                q_loc[nb][p] += __shfl_xor_sync(0xFFFFFFFFu, q_loc[nb][p], off);
            }
        }
    __syncthreads();
    float* sm_s = (float*)smem;          // [4][128]
    float* sm_q = sm_s + 512;            // [4][128]
    if (lane < 4) {
        #pragma unroll
        for (int nb = 0; nb < 4; nb++)
            #pragma unroll
            for (int p = 0; p < 2; p++) {
                int idx = wn * 32 + nb * 8 + lane * 2 + p;
                sm_s[wm * 128 + idx] = s_loc[nb][p];
                sm_q[wm * 128 + idx] = q_loc[nb][p];
            }
    }
    __syncthreads();
    if (tid < 128) {
        float s = ((sm_s[tid] + sm_s[128 + tid]) + sm_s[256 + tid]) + sm_s[384 + tid];
        float q = ((sm_q[tid] + sm_q[128 + tid]) + sm_q[256 + tid]) + sm_q[384 + tid];
        size_t gidx = (size_t)blockIdx.y * H_DIM + nbase + tid;
        g_psum[gidx] = s;
        g_psq [gidx] = q;
    }
}

// ---------------- stats finalize: reduce 256 mtile partials ----------------
__global__ void __launch_bounds__(256) k_stats_fin(const float* __restrict__ gamma,
                                                   const float* __restrict__ beta) {
    int j = blockIdx.x * 256 + threadIdx.x;
    float s = 0.f, q = 0.f;
    for (int p = 0; p < MTILES; p++) {
        s += g_psum[(size_t)p * H_DIM + j];
        q += g_psq [(size_t)p * H_DIM + j];
    }
    float mean = s * (1.f / B_DIM);
    float var  = q * (1.f / B_DIM) - mean * mean;
    float a = gamma[j] * rsqrtf(var + 1e-5f);
    float t; unsigned neg;
    if (a != 0.f) { t = mean - beta[j] / a; neg = (a < 0.f) ? 1u : 0u; }
    else { t = (beta[j] > 0.f) ? -__int_as_float(0x7f800000) : __int_as_float(0x7f800000); neg = 0u; }
    g_thr[j] = t;
    unsigned word = __ballot_sync(0xFFFFFFFFu, neg);
    if ((threadIdx.x & 31) == 0) g_negw[j >> 5] = word;
}

// ---------------- fused sign / XOR-popcount GEMM2 / log-softmax ----------------
__global__ void __launch_bounds__(128) k_final(float* __restrict__ out) {
    int row = blockIdx.x;
    __shared__ unsigned hw[128];
    __shared__ int wsum[4][OUT_DIM];
    int tid = threadIdx.x, lane = tid & 31, w = tid >> 5;
    const float* hr = g_h + (size_t)row * H_DIM;
    for (int c = w; c < 128; c += 4) {
        int col = c * 32 + lane;
        unsigned bit = (hr[col] > g_thr[col]) ? 1u : 0u;
        unsigned word = __ballot_sync(0xFFFFFFFFu, bit);
        if (lane == 0) hw[c] = word ^ g_negw[c];
    }
    __syncthreads();
    unsigned mw = hw[tid];
    #pragma unroll
    for (int o = 0; o < OUT_DIM; o++) {
        int v = __popc(mw ^ g_w2b[o * 128 + tid]);
        v = (int)__reduce_add_sync(0xFFFFFFFFu, (unsigned)v);
        if (lane == 0) wsum[w][o] = v;
    }
    __syncthreads();
    if (tid == 0) {
        float lg[OUT_DIM], mx = -3.4e38f;
        #pragma unroll
        for (int o = 0; o < OUT_DIM; o++) {
            int mis = wsum[0][o] + wsum[1][o] + wsum[2][o] + wsum[3][o];
            lg[o] = (float)(H_DIM - 2 * mis);
            mx = fmaxf(mx, lg[o]);
        }
        float se = 0.f;
        #pragma unroll
        for (int o = 0; o < OUT_DIM; o++) se += expf(lg[o] - mx);
        float lse = mx + logf(se);
        #pragma unroll
        for (int o = 0; o < OUT_DIM; o++) out[(size_t)row * OUT_DIM + o] = lg[o] - lse;
    }
}

// ---------------- launch ----------------
extern "C" void kernel_launch(void* const* d_in, const int* in_sizes, int n_in,
                              void* d_out, int out_size) {
    (void)in_sizes; (void)n_in; (void)out_size;
    const float* x     = (const float*)d_in[0];
    const float* W1    = (const float*)d_in[1];
    const float* gamma = (const float*)d_in[2];
    const float* beta  = (const float*)d_in[3];
    const float* W2    = (const float*)d_in[4];

    cudaFuncSetAttribute(k_gemm1, cudaFuncAttributeMaxDynamicSharedMemorySize, SMEM_TOTAL);

    {
        size_t n = (size_t)B_DIM * (KPAD / 4);
        k_prep_a<<<(unsigned)((n + 255) / 256), 256>>>(x);
    }
    {
        size_t n = (size_t)H_DIM * (KPAD / 4);
        k_prep_w<<<(unsigned)((n + 255) / 256), 256>>>(W1);
    }
    k_prep_w2<<<10, 128>>>(W2);

    k_gemm1<<<dim3(H_DIM / NT, B_DIM / MT), 512, SMEM_TOTAL>>>();

    k_stats_fin<<<H_DIM / 256, 256>>>(gamma, beta);

    k_final<<<B_DIM, 128>>>((float*)d_out);
}

// round 12
// speedup vs baseline: 1.0136x; 1.0136x over previous
#include <cuda_runtime.h>
#include <cstdint>
#include <math.h>

#define B_DIM   16384
#define IN_DIM  784
#define H_DIM   4096
#define OUT_DIM 10
#define KPAD    832            // 784 padded to 13*64
#define NCHUNK  13             // K chunks of 64
#define MT      64
#define NT      64
#define STAGES  4
#define MTILES  (B_DIM / MT)   // 256

// smem stage: A limbs [3][64 rows][80B] + B [64 rows][80B]
#define A_ROWB      80
#define A_LIMB_B    (64 * A_ROWB)            // 5120
#define STAGE_A_B   (3 * A_LIMB_B)           // 15360
#define STAGE_B_B   (64 * A_ROWB)            // 5120
#define STAGE_BYTES (STAGE_A_B + STAGE_B_B)  // 20480
#define SMEM_TOTAL  (STAGES * STAGE_BYTES)   // 81920 per CTA (2 CTAs/SM)

// ---------------- scratch ----------------
__device__ __align__(1024) int8_t g_Aq[(size_t)B_DIM * 3 * KPAD];   // 40.9 MB
__device__ __align__(1024) int8_t g_Bs[(size_t)H_DIM * KPAD];       // 3.4 MB
__device__ __align__(1024) float  g_h[(size_t)B_DIM * H_DIM];       // 268 MB
__device__ float    g_psum[MTILES * H_DIM];
__device__ float    g_psq [MTILES * H_DIM];
__device__ float    g_thr [H_DIM];
__device__ unsigned g_negw[H_DIM / 32];
__device__ unsigned g_w2b [OUT_DIM * (H_DIM / 32)];

// ---------------- helpers ----------------
__device__ __forceinline__ uint32_t smem_u32(const void* p) {
    uint32_t a;
    asm("{ .reg .u64 t; cvta.to.shared.u64 t, %1; cvt.u32.u64 %0, t; }" : "=r"(a) : "l"(p));
    return a;
}
__device__ __forceinline__ void cp_async16(uint32_t dst, const void* src) {
    asm volatile("cp.async.cg.shared.global [%0], [%1], 16;" :: "r"(dst), "l"(src) : "memory");
}
__device__ __forceinline__ void cp_commit() {
    asm volatile("cp.async.commit_group;" ::: "memory");
}
__device__ __forceinline__ void ldsm4(uint32_t addr, uint32_t* r) {
    asm volatile("ldmatrix.sync.aligned.m8n8.x4.shared.b16 {%0,%1,%2,%3}, [%4];"
                 : "=r"(r[0]), "=r"(r[1]), "=r"(r[2]), "=r"(r[3]) : "r"(addr));
}
__device__ __forceinline__ void imma(int* d, const uint32_t* a, const uint32_t* b) {
    asm volatile(
        "mma.sync.aligned.m16n8k32.row.col.s32.s8.s8.s32 "
        "{%0,%1,%2,%3}, {%4,%5,%6,%7}, {%8,%9}, {%0,%1,%2,%3};"
        : "+r"(d[0]), "+r"(d[1]), "+r"(d[2]), "+r"(d[3])
        : "r"(a[0]), "r"(a[1]), "r"(a[2]), "r"(a[3]), "r"(b[0]), "r"(b[1]));
}

// ---------------- prep: x -> 3 int8 limbs at scale 2^-20 ----------------
__global__ void k_prep_a(const float* __restrict__ x) {
    size_t i = (size_t)blockIdx.x * blockDim.x + threadIdx.x;
    if (i >= (size_t)B_DIM * (KPAD / 4)) return;
    int row = (int)(i / (KPAD / 4));
    int k4  = (int)(i % (KPAD / 4));
    int k   = k4 * 4;
    char4 l0 = make_char4(0, 0, 0, 0), l1 = l0, l2 = l0;
    if (k < IN_DIM) {
        float4 xv = *(const float4*)(x + (size_t)row * IN_DIM + k);
        float v[4] = {xv.x, xv.y, xv.z, xv.w};
        signed char a0[4], a1[4], a2[4];
        #pragma unroll
        for (int j = 0; j < 4; j++) {
            int q = __float2int_rn(v[j] * 1048576.0f);
            q = max(min(q, 8388607), -8388607);
            int b0 = (q << 24) >> 24;
            int q1 = (q - b0) >> 8;
            int b1 = (q1 << 24) >> 24;
            int b2 = (q1 - b1) >> 8;
            a0[j] = (signed char)b0; a1[j] = (signed char)b1; a2[j] = (signed char)b2;
        }
        l0 = make_char4(a0[0], a0[1], a0[2], a0[3]);
        l1 = make_char4(a1[0], a1[1], a1[2], a1[3]);
        l2 = make_char4(a2[0], a2[1], a2[2], a2[3]);
    }
    size_t base = (size_t)row * 3 * KPAD + k;
    *(char4*)(g_Aq + base)            = l0;
    *(char4*)(g_Aq + base + KPAD)     = l1;
    *(char4*)(g_Aq + base + 2 * KPAD) = l2;
}

__global__ void k_prep_w(const float* __restrict__ W1) {
    size_t i = (size_t)blockIdx.x * blockDim.x + threadIdx.x;
    if (i >= (size_t)H_DIM * (KPAD / 4)) return;
    int row = (int)(i / (KPAD / 4));
    int k4  = (int)(i % (KPAD / 4));
    int k   = k4 * 4;
    char4 s = make_char4(0, 0, 0, 0);
    if (k < IN_DIM) {
        float4 wv = *(const float4*)(W1 + (size_t)row * IN_DIM + k);
        float v[4] = {wv.x, wv.y, wv.z, wv.w};
        signed char sc[4];
        #pragma unroll
        for (int j = 0; j < 4; j++)
            sc[j] = (signed char)((v[j] > 0.f) ? 1 : ((v[j] < 0.f) ? -1 : 0));
        s = make_char4(sc[0], sc[1], sc[2], sc[3]);
    }
    *(char4*)(g_Bs + (size_t)row * KPAD + k) = s;
}

__global__ void k_prep_w2(const float* __restrict__ W2) {
    int idx = blockIdx.x * blockDim.x + threadIdx.x;
    if (idx >= OUT_DIM * 128) return;
    int o = idx / 128, w = idx % 128;
    unsigned bits = 0;
    for (int j = 0; j < 32; j++)
        if (W2[(size_t)o * H_DIM + w * 32 + j] > 0.f) bits |= (1u << j);
    g_w2b[idx] = bits;
}

// ---------------- GEMM1: 256-thread CTAs, 2 CTAs/SM, M64xN64 tile ----------------
__global__ void __launch_bounds__(256, 2) k_gemm1() {
    extern __shared__ __align__(128) char smem[];
    const uint32_t sb = smem_u32(smem);
    const int tid = threadIdx.x, lane = tid & 31, wid = tid >> 5;
    const int wm = wid & 3, wn = wid >> 2;       // 4 x 2 warp grid
    const int mbase = blockIdx.y * MT;
    const int nbase = blockIdx.x * NT;

    // cp.async granule plan: 1024 granules/stage, 4 per thread (g = tid + i*256)
    const int8_t* gsrc[4];
    uint32_t sdst[4];
    #pragma unroll
    for (int i = 0; i < 4; i++) {
        int g = tid + i * 256;
        if (g < 768) {
            int limb = g >> 8, rem = g & 255, row = rem >> 2, c = rem & 3;
            gsrc[i] = g_Aq + ((size_t)(mbase + row) * 3 + limb) * KPAD + c * 16;
            sdst[i] = limb * A_LIMB_B + row * A_ROWB + c * 16;
        } else {
            int gb = g - 768, row = gb >> 2, c = gb & 3;
            gsrc[i] = g_Bs + (size_t)(nbase + row) * KPAD + c * 16;
            sdst[i] = STAGE_A_B + row * A_ROWB + c * 16;
        }
    }

    // ldmatrix lane offsets
    const int mi = lane >> 3, r8 = lane & 7;
    const uint32_t aLane = (uint32_t)(((mi & 1) * 8 + r8) * A_ROWB + (mi >> 1) * 16);
    const uint32_t bLane = (uint32_t)(r8 * A_ROWB + (mi & 1) * 16 + (mi >> 1) * 32);
    const uint32_t aWarp = (uint32_t)(wm * 16 * A_ROWB) + aLane;
    const uint32_t bWarp = (uint32_t)(wn * 32 * A_ROWB) + bLane;

    int d[3][4][4];
    #pragma unroll
    for (int l = 0; l < 3; l++)
        #pragma unroll
        for (int nb = 0; nb < 4; nb++)
            #pragma unroll
            for (int i = 0; i < 4; i++) d[l][nb][i] = 0;

    // prologue: cp.async stages 0..2
    #pragma unroll
    for (int s = 0; s < STAGES - 1; s++) {
        #pragma unroll
        for (int i = 0; i < 4; i++)
            cp_async16(sb + s * STAGE_BYTES + sdst[i], gsrc[i] + s * 64);
        cp_commit();
    }

    uint32_t bfr[2][4][4];              // double-buffered B fragments
    uint32_t afr[3][2][4];              // A fragments, reloaded per-limb

    // wait for stage 0, load chunk-0 fragments
    asm volatile("cp.async.wait_group 2;" ::: "memory");
    __syncthreads();
    {
        const uint32_t sA = sb, sB = sb + STAGE_A_B;
        #pragma unroll
        for (int nb = 0; nb < 4; nb++)
            ldsm4(sB + bWarp + (uint32_t)(nb * 8 * A_ROWB), bfr[0][nb]);
        #pragma unroll
        for (int l = 0; l < 3; l++)
            #pragma unroll
            for (int ks = 0; ks < 2; ks++)
                ldsm4(sA + l * A_LIMB_B + aWarp + (uint32_t)(ks * 32), afr[l][ks]);
    }

    for (int kc = 0; kc < NCHUNK; kc++) {
        const int cur = kc & 1, nxt = cur ^ 1;

        // prefetch smem stage kc+3
        if (kc + 3 < NCHUNK) {
            int s = (kc + 3) % STAGES;
            #pragma unroll
            for (int i = 0; i < 4; i++)
                cp_async16(sb + s * STAGE_BYTES + sdst[i], gsrc[i] + (kc + 3) * 64);
            cp_commit();
        }

        const uint32_t sAn = sb + ((kc + 1) % STAGES) * STAGE_BYTES;
        const uint32_t sBn = sAn + STAGE_A_B;

        if (kc + 1 < NCHUNK) {
            // make stage kc+1 visible
            if (kc <= 9)       asm volatile("cp.async.wait_group 2;" ::: "memory");
            else if (kc == 10) asm volatile("cp.async.wait_group 1;" ::: "memory");
            else               asm volatile("cp.async.wait_group 0;" ::: "memory");
            __syncthreads();
            // B fragments for chunk kc+1 (into alternate buffer)
            #pragma unroll
            for (int nb = 0; nb < 4; nb++)
                ldsm4(sBn + bWarp + (uint32_t)(nb * 8 * A_ROWB), bfr[nxt][nb]);
        }

        // MMAs for chunk kc; A reloads for kc+1 interleaved behind each limb
        #pragma unroll
        for (int l = 0; l < 3; l++) {
            #pragma unroll
            for (int ks = 0; ks < 2; ks++)
                #pragma unroll
                for (int nb = 0; nb < 4; nb++)
                    imma(d[l][nb], afr[l][ks], &bfr[cur][nb][ks * 2]);
            if (kc + 1 < NCHUNK) {
                #pragma unroll
                for (int ks = 0; ks < 2; ks++)
                    ldsm4(sAn + l * A_LIMB_B + aWarp + (uint32_t)(ks * 32), afr[l][ks]);
            }
        }
    }

    // ---- epilogue: h = (65536*S2 + 256*S1 + S0) * 2^-20 + fused column stats ----
    float s_loc[4][2], q_loc[4][2];
    #pragma unroll
    for (int nb = 0; nb < 4; nb++) { s_loc[nb][0] = s_loc[nb][1] = 0.f; q_loc[nb][0] = q_loc[nb][1] = 0.f; }

    {
        int row0 = mbase + wm * 16 + (lane >> 2);
        #pragma unroll
        for (int nb = 0; nb < 4; nb++) {
            int col = nbase + wn * 32 + nb * 8 + (lane & 3) * 2;
            float f[4];
            #pragma unroll
            for (int i = 0; i < 4; i++)
                f[i] = fmaf((float)d[2][nb][i], 65536.f,
                            fmaf((float)d[1][nb][i], 256.f,
                                 (float)d[0][nb][i])) * (1.f / 1048576.f);
            *(float2*)(g_h + (size_t)row0 * H_DIM + col)       = make_float2(f[0], f[1]);
            *(float2*)(g_h + (size_t)(row0 + 8) * H_DIM + col) = make_float2(f[2], f[3]);
            s_loc[nb][0] += f[0] + f[2];            q_loc[nb][0] += f[0] * f[0] + f[2] * f[2];
            s_loc[nb][1] += f[1] + f[3];            q_loc[nb][1] += f[1] * f[1] + f[3] * f[3];
        }
    }
    // reduce across the 8 row-groups within the warp
    #pragma unroll
    for (int nb = 0; nb < 4; nb++)
        #pragma unroll
        for (int p = 0; p < 2; p++) {
            #pragma unroll
            for (int off = 4; off <= 16; off <<= 1) {
                s_loc[nb][p] += __shfl_xor_sync(0xFFFFFFFFu, s_loc[nb][p], off);
                q_loc[nb][p] += __shfl_xor_sync(0xFFFFFFFFu, q_loc[nb][p], off);
            }
        }
    // combine 4 wm groups through smem (fixed order -> deterministic)
    __syncthreads();
    float* sm_s = (float*)smem;          // [4][64]
    float* sm_q = sm_s + 256;            // [4][64]
    if (lane < 4) {
        #pragma unroll
        for (int nb = 0; nb < 4; nb++)
            #pragma unroll
            for (int p = 0; p < 2; p++) {
                int idx = wn * 32 + nb * 8 + lane * 2 + p;
                sm_s[wm * 64 + idx] = s_loc[nb][p];
                sm_q[wm * 64 + idx] = q_loc[nb][p];
            }
    }
    __syncthreads();
    if (tid < 64) {
        float s = ((sm_s[tid] + sm_s[64 + tid]) + sm_s[128 + tid]) + sm_s[192 + tid];
        float q = ((sm_q[tid] + sm_q[64 + tid]) + sm_q[128 + tid]) + sm_q[192 + tid];
        size_t gidx = (size_t)blockIdx.y * H_DIM + nbase + tid;
        g_psum[gidx] = s;
        g_psq [gidx] = q;
    }
}

// ---------------- stats finalize: reduce 256 mtile partials ----------------
__global__ void __launch_bounds__(256) k_stats_fin(const float* __restrict__ gamma,
                                                   const float* __restrict__ beta) {
    int j = blockIdx.x * 256 + threadIdx.x;
    float s = 0.f, q = 0.f;
    for (int p = 0; p < MTILES; p++) {
        s += g_psum[(size_t)p * H_DIM + j];
        q += g_psq [(size_t)p * H_DIM + j];
    }
    float mean = s * (1.f / B_DIM);
    float var  = q * (1.f / B_DIM) - mean * mean;
    float a = gamma[j] * rsqrtf(var + 1e-5f);
    float t; unsigned neg;
    if (a != 0.f) { t = mean - beta[j] / a; neg = (a < 0.f) ? 1u : 0u; }
    else { t = (beta[j] > 0.f) ? -__int_as_float(0x7f800000) : __int_as_float(0x7f800000); neg = 0u; }
    g_thr[j] = t;
    unsigned word = __ballot_sync(0xFFFFFFFFu, neg);
    if ((threadIdx.x & 31) == 0) g_negw[j >> 5] = word;
}

// ---------------- fused sign / XOR-popcount GEMM2 / log-softmax ----------------
__global__ void __launch_bounds__(128) k_final(float* __restrict__ out) {
    int row = blockIdx.x;
    __shared__ unsigned hw[128];
    __shared__ int wsum[4][OUT_DIM];
    int tid = threadIdx.x, lane = tid & 31, w = tid >> 5;
    const float* hr = g_h + (size_t)row * H_DIM;
    for (int c = w; c < 128; c += 4) {
        int col = c * 32 + lane;
        unsigned bit = (hr[col] > g_thr[col]) ? 1u : 0u;
        unsigned word = __ballot_sync(0xFFFFFFFFu, bit);
        if (lane == 0) hw[c] = word ^ g_negw[c];
    }
    __syncthreads();
    unsigned mw = hw[tid];
    #pragma unroll
    for (int o = 0; o < OUT_DIM; o++) {
        int v = __popc(mw ^ g_w2b[o * 128 + tid]);
        v = (int)__reduce_add_sync(0xFFFFFFFFu, (unsigned)v);
        if (lane == 0) wsum[w][o] = v;
    }
    __syncthreads();
    if (tid == 0) {
        float lg[OUT_DIM], mx = -3.4e38f;
        #pragma unroll
        for (int o = 0; o < OUT_DIM; o++) {
            int mis = wsum[0][o] + wsum[1][o] + wsum[2][o] + wsum[3][o];
            lg[o] = (float)(H_DIM - 2 * mis);
            mx = fmaxf(mx, lg[o]);
        }
        float se = 0.f;
        #pragma unroll
        for (int o = 0; o < OUT_DIM; o++) se += expf(lg[o] - mx);
        float lse = mx + logf(se);
        #pragma unroll
        for (int o = 0; o < OUT_DIM; o++) out[(size_t)row * OUT_DIM + o] = lg[o] - lse;
    }
}

// ---------------- launch ----------------
extern "C" void kernel_launch(void* const* d_in, const int* in_sizes, int n_in,
                              void* d_out, int out_size) {
    (void)in_sizes; (void)n_in; (void)out_size;
    const float* x     = (const float*)d_in[0];
    const float* W1    = (const float*)d_in[1];
    const float* gamma = (const float*)d_in[2];
    const float* beta  = (const float*)d_in[3];
    const float* W2    = (const float*)d_in[4];

    cudaFuncSetAttribute(k_gemm1, cudaFuncAttributeMaxDynamicSharedMemorySize, SMEM_TOTAL);

    {
        size_t n = (size_t)B_DIM * (KPAD / 4);
        k_prep_a<<<(unsigned)((n + 255) / 256), 256>>>(x);
    }
    {
        size_t n = (size_t)H_DIM * (KPAD / 4);
        k_prep_w<<<(unsigned)((n + 255) / 256), 256>>>(W1);
    }
    k_prep_w2<<<10, 128>>>(W2);

    k_gemm1<<<dim3(H_DIM / NT, B_DIM / MT), 256, SMEM_TOTAL>>>();

    k_stats_fin<<<H_DIM / 256, 256>>>(gamma, beta);

    k_final<<<B_DIM, 128>>>((float*)d_out);
}

// round 15
// speedup vs baseline: 1.0333x; 1.0194x over previous
#include <cuda_runtime.h>
#include <cstdint>
#include <math.h>

#define B_DIM   16384
#define IN_DIM  784
#define H_DIM   4096
#define OUT_DIM 10
#define KPAD    832            // 784 padded to 13*64
#define NCHUNK  13             // K chunks of 64
#define MT      64
#define NT      128
#define STAGES  4
#define MTILES  (B_DIM / MT)   // 256

// smem stage layout: A limbs [3][64 rows][80B], B [128 rows][80B]
#define A_ROWB      80
#define A_LIMB_B    (64 * A_ROWB)            // 5120
#define STAGE_A_B   (3 * A_LIMB_B)           // 15360
#define STAGE_B_B   (128 * A_ROWB)           // 10240
#define STAGE_BYTES (STAGE_A_B + STAGE_B_B)  // 25600
#define SMEM_TOTAL  (STAGES * STAGE_BYTES)   // 102400

// prep work partition
#define PREP_A_N   ((size_t)B_DIM * (KPAD / 4))   // 3407872
#define PREP_W_N   ((size_t)H_DIM * (KPAD / 4))   // 851968
#define PREP_W2_N  (OUT_DIM * 128)                // 1280
#define PREP_TOTAL (PREP_A_N + PREP_W_N + PREP_W2_N)

// ---------------- scratch ----------------
__device__ __align__(1024) int8_t g_Aq[(size_t)B_DIM * 3 * KPAD];   // 40.9 MB
__device__ __align__(1024) int8_t g_Bs[(size_t)H_DIM * KPAD];       // 3.4 MB
__device__ __align__(1024) float  g_h[(size_t)B_DIM * H_DIM];       // 268 MB
__device__ float    g_psum[MTILES * H_DIM];
__device__ float    g_psq [MTILES * H_DIM];
__device__ float    g_thr [H_DIM];
__device__ unsigned g_negw[H_DIM / 32];
__device__ unsigned g_w2b [OUT_DIM * (H_DIM / 32)];

// ---------------- helpers ----------------
__device__ __forceinline__ uint32_t smem_u32(const void* p) {
    uint32_t a;
    asm("{ .reg .u64 t; cvta.to.shared.u64 t, %1; cvt.u32.u64 %0, t; }" : "=r"(a) : "l"(p));
    return a;
}
__device__ __forceinline__ void cp_async16(uint32_t dst, const void* src) {
    asm volatile("cp.async.cg.shared.global [%0], [%1], 16;" :: "r"(dst), "l"(src) : "memory");
}
__device__ __forceinline__ void cp_commit() {
    asm volatile("cp.async.commit_group;" ::: "memory");
}
__device__ __forceinline__ void ldsm4(uint32_t addr, uint32_t* r) {
    asm volatile("ldmatrix.sync.aligned.m8n8.x4.shared.b16 {%0,%1,%2,%3}, [%4];"
                 : "=r"(r[0]), "=r"(r[1]), "=r"(r[2]), "=r"(r[3]) : "r"(addr));
}
__device__ __forceinline__ void imma(int* d, const uint32_t* a, const uint32_t* b) {
    asm volatile(
        "mma.sync.aligned.m16n8k32.row.col.s32.s8.s8.s32 "
        "{%0,%1,%2,%3}, {%4,%5,%6,%7}, {%8,%9}, {%0,%1,%2,%3};"
        : "+r"(d[0]), "+r"(d[1]), "+r"(d[2]), "+r"(d[3])
        : "r"(a[0]), "r"(a[1]), "r"(a[2]), "r"(a[3]), "r"(b[0]), "r"(b[1]));
}
__device__ __forceinline__ void stcs2(float* p, float2 v) {
    asm volatile("st.global.cs.v2.f32 [%0], {%1, %2};" :: "l"(p), "f"(v.x), "f"(v.y) : "memory");
}

// ---------------- merged prep: A limbs + W1 signs + W2 bitpack ----------------
__global__ void k_prep(const float* __restrict__ x, const float* __restrict__ W1,
                       const float* __restrict__ W2) {
    size_t i = (size_t)blockIdx.x * blockDim.x + threadIdx.x;
    if (i < PREP_A_N) {
        int row = (int)(i / (KPAD / 4));
        int k   = (int)(i % (KPAD / 4)) * 4;
        char4 l0 = make_char4(0, 0, 0, 0), l1 = l0, l2 = l0;
        if (k < IN_DIM) {
            float4 xv = *(const float4*)(x + (size_t)row * IN_DIM + k);
            float v[4] = {xv.x, xv.y, xv.z, xv.w};
            signed char a0[4], a1[4], a2[4];
            #pragma unroll
            for (int j = 0; j < 4; j++) {
                int q = __float2int_rn(v[j] * 1048576.0f);
                q = max(min(q, 8388607), -8388607);
                int b0 = (q << 24) >> 24;
                int q1 = (q - b0) >> 8;
                int b1 = (q1 << 24) >> 24;
                int b2 = (q1 - b1) >> 8;
                a0[j] = (signed char)b0; a1[j] = (signed char)b1; a2[j] = (signed char)b2;
            }
            l0 = make_char4(a0[0], a0[1], a0[2], a0[3]);
            l1 = make_char4(a1[0], a1[1], a1[2], a1[3]);
            l2 = make_char4(a2[0], a2[1], a2[2], a2[3]);
        }
        size_t base = (size_t)row * 3 * KPAD + k;
        *(char4*)(g_Aq + base)            = l0;
        *(char4*)(g_Aq + base + KPAD)     = l1;
        *(char4*)(g_Aq + base + 2 * KPAD) = l2;
        return;
    }
    size_t j = i - PREP_A_N;
    if (j < PREP_W_N) {
        int row = (int)(j / (KPAD / 4));
        int k   = (int)(j % (KPAD / 4)) * 4;
        char4 s = make_char4(0, 0, 0, 0);
        if (k < IN_DIM) {
            float4 wv = *(const float4*)(W1 + (size_t)row * IN_DIM + k);
            float v[4] = {wv.x, wv.y, wv.z, wv.w};
            signed char sc[4];
            #pragma unroll
            for (int t = 0; t < 4; t++)
                sc[t] = (signed char)((v[t] > 0.f) ? 1 : ((v[t] < 0.f) ? -1 : 0));
            s = make_char4(sc[0], sc[1], sc[2], sc[3]);
        }
        *(char4*)(g_Bs + (size_t)row * KPAD + k) = s;
        return;
    }
    size_t m = j - PREP_W_N;
    if (m < PREP_W2_N) {
        int o = (int)(m / 128), w = (int)(m % 128);
        unsigned bits = 0;
        for (int t = 0; t < 32; t++)
            if (W2[(size_t)o * H_DIM + w * 32 + t] > 0.f) bits |= (1u << t);
        g_w2b[m] = bits;
    }
}

// ---------------- GEMM1: R8 mainloop (512 threads, register-pipelined) ----------------
__global__ void __launch_bounds__(512, 1) k_gemm1() {
    extern __shared__ __align__(128) char smem[];
    const uint32_t sb = smem_u32(smem);
    const int tid = threadIdx.x, lane = tid & 31, wid = tid >> 5;
    const int wm = wid & 3, wn = wid >> 2;       // 4 x 4 warp grid
    const int mbase = blockIdx.y * MT;
    const int nbase = blockIdx.x * NT;

    // cp.async granule plan: 1280 granules/stage
    const int ng = (tid < 256) ? 3 : 2;
    const int8_t* gsrc[3];
    uint32_t sdst[3];
    #pragma unroll
    for (int i = 0; i < 3; i++) {
        int g = tid + i * 512;
        if (g >= 1280) g = 0;   // dummy (unused when i >= ng)
        if (g < 768) {
            int limb = g >> 8, rem = g & 255, row = rem >> 2, c = rem & 3;
            gsrc[i] = g_Aq + ((size_t)(mbase + row) * 3 + limb) * KPAD + c * 16;
            sdst[i] = limb * A_LIMB_B + row * A_ROWB + c * 16;
        } else {
            int gb = g - 768, row = gb >> 2, c = gb & 3;
            gsrc[i] = g_Bs + (size_t)(nbase + row) * KPAD + c * 16;
            sdst[i] = STAGE_A_B + row * A_ROWB + c * 16;
        }
    }

    // ldmatrix lane offsets
    const int mi = lane >> 3, r8 = lane & 7;
    const uint32_t aLane = (uint32_t)(((mi & 1) * 8 + r8) * A_ROWB + (mi >> 1) * 16);
    const uint32_t bLane = (uint32_t)(r8 * A_ROWB + (mi & 1) * 16 + (mi >> 1) * 32);
    const uint32_t aWarp = (uint32_t)(wm * 16 * A_ROWB) + aLane;
    const uint32_t bWarp = (uint32_t)(wn * 32 * A_ROWB) + bLane;

    int d[3][4][4];
    #pragma unroll
    for (int l = 0; l < 3; l++)
        #pragma unroll
        for (int nb = 0; nb < 4; nb++)
            #pragma unroll
            for (int i = 0; i < 4; i++) d[l][nb][i] = 0;

    // prologue: cp.async stages 0..2
    #pragma unroll
    for (int s = 0; s < STAGES - 1; s++) {
        #pragma unroll
        for (int i = 0; i < 3; i++)
            if (i < ng) cp_async16(sb + s * STAGE_BYTES + sdst[i], gsrc[i] + s * 64);
        cp_commit();
    }

    uint32_t bfr[2][4][4];              // double-buffered B fragments
    uint32_t afr[3][2][4];              // A fragments, reloaded per-limb

    // wait for stage 0, load chunk-0 fragments
    asm volatile("cp.async.wait_group 2;" ::: "memory");
    __syncthreads();
    {
        const uint32_t sA = sb, sB = sb + STAGE_A_B;
        #pragma unroll
        for (int nb = 0; nb < 4; nb++)
            ldsm4(sB + bWarp + (uint32_t)(nb * 8 * A_ROWB), bfr[0][nb]);
        #pragma unroll
        for (int l = 0; l < 3; l++)
            #pragma unroll
            for (int ks = 0; ks < 2; ks++)
                ldsm4(sA + l * A_LIMB_B + aWarp + (uint32_t)(ks * 32), afr[l][ks]);
    }

    for (int kc = 0; kc < NCHUNK; kc++) {
        const int cur = kc & 1, nxt = cur ^ 1;

        // prefetch smem stage kc+3
        if (kc + 3 < NCHUNK) {
            int s = (kc + 3) % STAGES;
            #pragma unroll
            for (int i = 0; i < 3; i++)
                if (i < ng) cp_async16(sb + s * STAGE_BYTES + sdst[i], gsrc[i] + (kc + 3) * 64);
            cp_commit();
        }

        const uint32_t sAn = sb + ((kc + 1) % STAGES) * STAGE_BYTES;
        const uint32_t sBn = sAn + STAGE_A_B;

        if (kc + 1 < NCHUNK) {
            // make stage kc+1 visible
            if (kc <= 9)       asm volatile("cp.async.wait_group 2;" ::: "memory");
            else if (kc == 10) asm volatile("cp.async.wait_group 1;" ::: "memory");
            else               asm volatile("cp.async.wait_group 0;" ::: "memory");
            __syncthreads();
            // B fragments for chunk kc+1 (into alternate buffer)
            #pragma unroll
            for (int nb = 0; nb < 4; nb++)
                ldsm4(sBn + bWarp + (uint32_t)(nb * 8 * A_ROWB), bfr[nxt][nb]);
        }

        // MMAs for chunk kc; A reloads for kc+1 interleaved behind each limb
        #pragma unroll
        for (int l = 0; l < 3; l++) {
            #pragma unroll
            for (int ks = 0; ks < 2; ks++)
                #pragma unroll
                for (int nb = 0; nb < 4; nb++)
                    imma(d[l][nb], afr[l][ks], &bfr[cur][nb][ks * 2]);
            if (kc + 1 < NCHUNK) {
                #pragma unroll
                for (int ks = 0; ks < 2; ks++)
                    ldsm4(sAn + l * A_LIMB_B + aWarp + (uint32_t)(ks * 32), afr[l][ks]);
            }
        }
    }

    // ---- epilogue: h = (65536*S2 + 256*S1 + S0) * 2^-20 + fused column stats ----
    float s_loc[4][2], q_loc[4][2];
    #pragma unroll
    for (int nb = 0; nb < 4; nb++) { s_loc[nb][0] = s_loc[nb][1] = 0.f; q_loc[nb][0] = q_loc[nb][1] = 0.f; }

    {
        int row0 = mbase + wm * 16 + (lane >> 2);
        #pragma unroll
        for (int nb = 0; nb < 4; nb++) {
            int col = nbase + wn * 32 + nb * 8 + (lane & 3) * 2;
            float f[4];
            #pragma unroll
            for (int i = 0; i < 4; i++)
                f[i] = fmaf((float)d[2][nb][i], 65536.f,
                            fmaf((float)d[1][nb][i], 256.f,
                                 (float)d[0][nb][i])) * (1.f / 1048576.f);
            stcs2(g_h + (size_t)row0 * H_DIM + col,       make_float2(f[0], f[1]));
            stcs2(g_h + (size_t)(row0 + 8) * H_DIM + col, make_float2(f[2], f[3]));
            s_loc[nb][0] += f[0] + f[2];            q_loc[nb][0] += f[0] * f[0] + f[2] * f[2];
            s_loc[nb][1] += f[1] + f[3];            q_loc[nb][1] += f[1] * f[1] + f[3] * f[3];
        }
    }
    #pragma unroll
    for (int nb = 0; nb < 4; nb++)
        #pragma unroll
        for (int p = 0; p < 2; p++) {
            #pragma unroll
            for (int off = 4; off <= 16; off <<= 1) {
                s_loc[nb][p] += __shfl_xor_sync(0xFFFFFFFFu, s_loc[nb][p], off);
                q_loc[nb][p] += __shfl_xor_sync(0xFFFFFFFFu, q_loc[nb][p], off);
            }
        }
    __syncthreads();
    float* sm_s = (float*)smem;          // [4][128]
    float* sm_q = sm_s + 512;            // [4][128]
    if (lane < 4) {
        #pragma unroll
        for (int nb = 0; nb < 4; nb++)
            #pragma unroll
            for (int p = 0; p < 2; p++) {
                int idx = wn * 32 + nb * 8 + lane * 2 + p;
                sm_s[wm * 128 + idx] = s_loc[nb][p];
                sm_q[wm * 128 + idx] = q_loc[nb][p];
            }
    }
    __syncthreads();
    if (tid < 128) {
        float s = ((sm_s[tid] + sm_s[128 + tid]) + sm_s[256 + tid]) + sm_s[384 + tid];
        float q = ((sm_q[tid] + sm_q[128 + tid]) + sm_q[256 + tid]) + sm_q[384 + tid];
        size_t gidx = (size_t)blockIdx.y * H_DIM + nbase + tid;
        g_psum[gidx] = s;
        g_psq [gidx] = q;
    }
}

// ---------------- stats finalize: reduce 256 mtile partials ----------------
__global__ void __launch_bounds__(256) k_stats_fin(const float* __restrict__ gamma,
                                                   const float* __restrict__ beta) {
    int j = blockIdx.x * 256 + threadIdx.x;
    float s = 0.f, q = 0.f;
    for (int p = 0; p < MTILES; p++) {
        s += g_psum[(size_t)p * H_DIM + j];
        q += g_psq [(size_t)p * H_DIM + j];
    }
    float mean = s * (1.f / B_DIM);
    float var  = q * (1.f / B_DIM) - mean * mean;
    float a = gamma[j] * rsqrtf(var + 1e-5f);
    float t; unsigned neg;
    if (a != 0.f) { t = mean - beta[j] / a; neg = (a < 0.f) ? 1u : 0u; }
    else { t = (beta[j] > 0.f) ? -__int_as_float(0x7f800000) : __int_as_float(0x7f800000); neg = 0u; }
    g_thr[j] = t;
    unsigned word = __ballot_sync(0xFFFFFFFFu, neg);
    if ((threadIdx.x & 31) == 0) g_negw[j >> 5] = word;
}

// ---------------- fused sign / XOR-popcount GEMM2 / log-softmax (2 rows/block) ----------------
__global__ void __launch_bounds__(256) k_final(float* __restrict__ out) {
    __shared__ unsigned hw[2][128];
    __shared__ int wsum[2][4][OUT_DIM];
    int g = threadIdx.x >> 7;                 // row-group 0/1
    int tid = threadIdx.x & 127;
    int row = blockIdx.x * 2 + g;
    int lane = tid & 31, w = tid >> 5;
    const float* hr = g_h + (size_t)row * H_DIM;
    for (int c = w; c < 128; c += 4) {
        int col = c * 32 + lane;
        unsigned bit = (__ldcs(hr + col) > g_thr[col]) ? 1u : 0u;
        unsigned word = __ballot_sync(0xFFFFFFFFu, bit);
        if (lane == 0) hw[g][c] = word ^ g_negw[c];
    }
    __syncthreads();
    unsigned mw = hw[g][tid];
    #pragma unroll
    for (int o = 0; o < OUT_DIM; o++) {
        int v = __popc(mw ^ g_w2b[o * 128 + tid]);
        v = (int)__reduce_add_sync(0xFFFFFFFFu, (unsigned)v);
        if (lane == 0) wsum[g][w][o] = v;
    }
    __syncthreads();
    if (tid == 0) {
        float lg[OUT_DIM], mx = -3.4e38f;
        #pragma unroll
        for (int o = 0; o < OUT_DIM; o++) {
            int mis = wsum[g][0][o] + wsum[g][1][o] + wsum[g][2][o] + wsum[g][3][o];
            lg[o] = (float)(H_DIM - 2 * mis);
            mx = fmaxf(mx, lg[o]);
        }
        float se = 0.f;
        #pragma unroll
        for (int o = 0; o < OUT_DIM; o++) se += expf(lg[o] - mx);
        float lse = mx + logf(se);
        #pragma unroll
        for (int o = 0; o < OUT_DIM; o++) out[(size_t)row * OUT_DIM + o] = lg[o] - lse;
    }
}

// ---------------- launch ----------------
extern "C" void kernel_launch(void* const* d_in, const int* in_sizes, int n_in,
                              void* d_out, int out_size) {
    (void)in_sizes; (void)n_in; (void)out_size;
    const float* x     = (const float*)d_in[0];
    const float* W1    = (const float*)d_in[1];
    const float* gamma = (const float*)d_in[2];
    const float* beta  = (const float*)d_in[3];
    const float* W2    = (const float*)d_in[4];

    cudaFuncSetAttribute(k_gemm1, cudaFuncAttributeMaxDynamicSharedMemorySize, SMEM_TOTAL);

    k_prep<<<(unsigned)((PREP_TOTAL + 255) / 256), 256>>>(x, W1, W2);

    k_gemm1<<<dim3(H_DIM / NT, B_DIM / MT), 512, SMEM_TOTAL>>>();

    k_stats_fin<<<H_DIM / 256, 256>>>(gamma, beta);

    k_final<<<B_DIM / 2, 256>>>((float*)d_out);
}

// round 16
// speedup vs baseline: 1.0814x; 1.0466x over previous
#include <cuda_runtime.h>
#include <cstdint>
#include <math.h>

#define B_DIM   16384
#define IN_DIM  784
#define H_DIM   4096
#define OUT_DIM 10
#define KPAD    832            // 784 padded to 13*64
#define NCHUNK  13             // K chunks of 64
#define MT      64
#define NT      128
#define STAGES  4
#define MTILES  (B_DIM / MT)   // 256

// smem stage layout: A limbs [3][64 rows][80B], B [128 rows][80B]
#define A_ROWB      80
#define A_LIMB_B    (64 * A_ROWB)            // 5120
#define STAGE_A_B   (3 * A_LIMB_B)           // 15360
#define STAGE_B_B   (128 * A_ROWB)           // 10240
#define STAGE_BYTES (STAGE_A_B + STAGE_B_B)  // 25600
#define SMEM_TOTAL  (STAGES * STAGE_BYTES)   // 102400

// prep work partition
#define PREP_A_N   ((size_t)B_DIM * (KPAD / 4))   // 3407872
#define PREP_W_N   ((size_t)H_DIM * (KPAD / 4))   // 851968
#define PREP_W2_N  (OUT_DIM * 128)                // 1280
#define PREP_TOTAL (PREP_A_N + PREP_W_N + PREP_W2_N)

// ---------------- scratch ----------------
__device__ __align__(1024) int8_t g_Aq[(size_t)B_DIM * 3 * KPAD];   // 40.9 MB
__device__ __align__(1024) int8_t g_Bs[(size_t)H_DIM * KPAD];       // 3.4 MB
__device__ __align__(1024) float  g_h[(size_t)B_DIM * H_DIM];       // 268 MB
__device__ float    g_psum[MTILES * H_DIM];
__device__ float    g_psq [MTILES * H_DIM];
__device__ float    g_thr [H_DIM];
__device__ unsigned g_negw[H_DIM / 32];
__device__ unsigned g_w2b [OUT_DIM * (H_DIM / 32)];

// ---------------- helpers ----------------
__device__ __forceinline__ uint32_t smem_u32(const void* p) {
    uint32_t a;
    asm("{ .reg .u64 t; cvta.to.shared.u64 t, %1; cvt.u32.u64 %0, t; }" : "=r"(a) : "l"(p));
    return a;
}
__device__ __forceinline__ void cp_async16(uint32_t dst, const void* src) {
    asm volatile("cp.async.cg.shared.global [%0], [%1], 16;" :: "r"(dst), "l"(src) : "memory");
}
__device__ __forceinline__ void cp_commit() {
    asm volatile("cp.async.commit_group;" ::: "memory");
}
__device__ __forceinline__ void ldsm4(uint32_t addr, uint32_t* r) {
    asm volatile("ldmatrix.sync.aligned.m8n8.x4.shared.b16 {%0,%1,%2,%3}, [%4];"
                 : "=r"(r[0]), "=r"(r[1]), "=r"(r[2]), "=r"(r[3]) : "r"(addr));
}
__device__ __forceinline__ void imma(int* d, const uint32_t* a, const uint32_t* b) {
    asm volatile(
        "mma.sync.aligned.m16n8k32.row.col.s32.s8.s8.s32 "
        "{%0,%1,%2,%3}, {%4,%5,%6,%7}, {%8,%9}, {%0,%1,%2,%3};"
        : "+r"(d[0]), "+r"(d[1]), "+r"(d[2]), "+r"(d[3])
        : "r"(a[0]), "r"(a[1]), "r"(a[2]), "r"(a[3]), "r"(b[0]), "r"(b[1]));
}
__device__ __forceinline__ void stcs2(float* p, float2 v) {
    asm volatile("st.global.cs.v2.f32 [%0], {%1, %2};" :: "l"(p), "f"(v.x), "f"(v.y) : "memory");
}

// ---------------- merged prep: A limbs + W1 signs + W2 bitpack ----------------
__global__ void k_prep(const float* __restrict__ x, const float* __restrict__ W1,
                       const float* __restrict__ W2) {
    size_t i = (size_t)blockIdx.x * blockDim.x + threadIdx.x;
    if (i < PREP_A_N) {
        int row = (int)(i / (KPAD / 4));
        int k   = (int)(i % (KPAD / 4)) * 4;
        char4 l0 = make_char4(0, 0, 0, 0), l1 = l0, l2 = l0;
        if (k < IN_DIM) {
            float4 xv = *(const float4*)(x + (size_t)row * IN_DIM + k);
            float v[4] = {xv.x, xv.y, xv.z, xv.w};
            signed char a0[4], a1[4], a2[4];
            #pragma unroll
            for (int j = 0; j < 4; j++) {
                int q = __float2int_rn(v[j] * 1048576.0f);
                q = max(min(q, 8388607), -8388607);
                int b0 = (q << 24) >> 24;
                int q1 = (q - b0) >> 8;
                int b1 = (q1 << 24) >> 24;
                int b2 = (q1 - b1) >> 8;
                a0[j] = (signed char)b0; a1[j] = (signed char)b1; a2[j] = (signed char)b2;
            }
            l0 = make_char4(a0[0], a0[1], a0[2], a0[3]);
            l1 = make_char4(a1[0], a1[1], a1[2], a1[3]);
            l2 = make_char4(a2[0], a2[1], a2[2], a2[3]);
        }
        size_t base = (size_t)row * 3 * KPAD + k;
        *(char4*)(g_Aq + base)            = l0;
        *(char4*)(g_Aq + base + KPAD)     = l1;
        *(char4*)(g_Aq + base + 2 * KPAD) = l2;
        return;
    }
    size_t j = i - PREP_A_N;
    if (j < PREP_W_N) {
        int row = (int)(j / (KPAD / 4));
        int k   = (int)(j % (KPAD / 4)) * 4;
        char4 s = make_char4(0, 0, 0, 0);
        if (k < IN_DIM) {
            float4 wv = *(const float4*)(W1 + (size_t)row * IN_DIM + k);
            float v[4] = {wv.x, wv.y, wv.z, wv.w};
            signed char sc[4];
            #pragma unroll
            for (int t = 0; t < 4; t++)
                sc[t] = (signed char)((v[t] > 0.f) ? 1 : ((v[t] < 0.f) ? -1 : 0));
            s = make_char4(sc[0], sc[1], sc[2], sc[3]);
        }
        *(char4*)(g_Bs + (size_t)row * KPAD + k) = s;
        return;
    }
    size_t m = j - PREP_W_N;
    if (m < PREP_W2_N) {
        int o = (int)(m / 128), w = (int)(m % 128);
        unsigned bits = 0;
        for (int t = 0; t < 32; t++)
            if (W2[(size_t)o * H_DIM + w * 32 + t] > 0.f) bits |= (1u << t);
        g_w2b[m] = bits;
    }
}

// ---------------- GEMM1: R8 mainloop (512 threads, register-pipelined) ----------------
__global__ void __launch_bounds__(512, 1) k_gemm1() {
    extern __shared__ __align__(128) char smem[];
    const uint32_t sb = smem_u32(smem);
    const int tid = threadIdx.x, lane = tid & 31, wid = tid >> 5;
    const int wm = wid & 3, wn = wid >> 2;       // 4 x 4 warp grid
    const int mbase = blockIdx.y * MT;
    const int nbase = blockIdx.x * NT;

    // cp.async granule plan: 1280 granules/stage
    const int ng = (tid < 256) ? 3 : 2;
    const int8_t* gsrc[3];
    uint32_t sdst[3];
    #pragma unroll
    for (int i = 0; i < 3; i++) {
        int g = tid + i * 512;
        if (g >= 1280) g = 0;   // dummy (unused when i >= ng)
        if (g < 768) {
            int limb = g >> 8, rem = g & 255, row = rem >> 2, c = rem & 3;
            gsrc[i] = g_Aq + ((size_t)(mbase + row) * 3 + limb) * KPAD + c * 16;
            sdst[i] = limb * A_LIMB_B + row * A_ROWB + c * 16;
        } else {
            int gb = g - 768, row = gb >> 2, c = gb & 3;
            gsrc[i] = g_Bs + (size_t)(nbase + row) * KPAD + c * 16;
            sdst[i] = STAGE_A_B + row * A_ROWB + c * 16;
        }
    }

    // ldmatrix lane offsets
    const int mi = lane >> 3, r8 = lane & 7;
    const uint32_t aLane = (uint32_t)(((mi & 1) * 8 + r8) * A_ROWB + (mi >> 1) * 16);
    const uint32_t bLane = (uint32_t)(r8 * A_ROWB + (mi & 1) * 16 + (mi >> 1) * 32);
    const uint32_t aWarp = (uint32_t)(wm * 16 * A_ROWB) + aLane;
    const uint32_t bWarp = (uint32_t)(wn * 32 * A_ROWB) + bLane;

    int d[3][4][4];
    #pragma unroll
    for (int l = 0; l < 3; l++)
        #pragma unroll
        for (int nb = 0; nb < 4; nb++)
            #pragma unroll
            for (int i = 0; i < 4; i++) d[l][nb][i] = 0;

    // prologue: cp.async stages 0..2
    #pragma unroll
    for (int s = 0; s < STAGES - 1; s++) {
        #pragma unroll
        for (int i = 0; i < 3; i++)
            if (i < ng) cp_async16(sb + s * STAGE_BYTES + sdst[i], gsrc[i] + s * 64);
        cp_commit();
    }

    uint32_t bfr[2][4][4];              // double-buffered B fragments
    uint32_t afr[3][2][4];              // A fragments, reloaded per-limb

    // wait for stage 0, load chunk-0 fragments
    asm volatile("cp.async.wait_group 2;" ::: "memory");
    __syncthreads();
    {
        const uint32_t sA = sb, sB = sb + STAGE_A_B;
        #pragma unroll
        for (int nb = 0; nb < 4; nb++)
            ldsm4(sB + bWarp + (uint32_t)(nb * 8 * A_ROWB), bfr[0][nb]);
        #pragma unroll
        for (int l = 0; l < 3; l++)
            #pragma unroll
            for (int ks = 0; ks < 2; ks++)
                ldsm4(sA + l * A_LIMB_B + aWarp + (uint32_t)(ks * 32), afr[l][ks]);
    }

    for (int kc = 0; kc < NCHUNK; kc++) {
        const int cur = kc & 1, nxt = cur ^ 1;

        // prefetch smem stage kc+3
        if (kc + 3 < NCHUNK) {
            int s = (kc + 3) % STAGES;
            #pragma unroll
            for (int i = 0; i < 3; i++)
                if (i < ng) cp_async16(sb + s * STAGE_BYTES + sdst[i], gsrc[i] + (kc + 3) * 64);
            cp_commit();
        }

        const uint32_t sAn = sb + ((kc + 1) % STAGES) * STAGE_BYTES;
        const uint32_t sBn = sAn + STAGE_A_B;

        if (kc + 1 < NCHUNK) {
            // make stage kc+1 visible
            if (kc <= 9)       asm volatile("cp.async.wait_group 2;" ::: "memory");
            else if (kc == 10) asm volatile("cp.async.wait_group 1;" ::: "memory");
            else               asm volatile("cp.async.wait_group 0;" ::: "memory");
            __syncthreads();
            // B fragments for chunk kc+1 (into alternate buffer)
            #pragma unroll
            for (int nb = 0; nb < 4; nb++)
                ldsm4(sBn + bWarp + (uint32_t)(nb * 8 * A_ROWB), bfr[nxt][nb]);
        }

        // MMAs for chunk kc; A reloads for kc+1 interleaved behind each limb
        #pragma unroll
        for (int l = 0; l < 3; l++) {
            #pragma unroll
            for (int ks = 0; ks < 2; ks++)
                #pragma unroll
                for (int nb = 0; nb < 4; nb++)
                    imma(d[l][nb], afr[l][ks], &bfr[cur][nb][ks * 2]);
            if (kc + 1 < NCHUNK) {
                #pragma unroll
                for (int ks = 0; ks < 2; ks++)
                    ldsm4(sAn + l * A_LIMB_B + aWarp + (uint32_t)(ks * 32), afr[l][ks]);
            }
        }
    }

    // ---- epilogue: h = (65536*S2 + 256*S1 + S0) * 2^-20 + fused column stats ----
    float s_loc[4][2], q_loc[4][2];
    #pragma unroll
    for (int nb = 0; nb < 4; nb++) { s_loc[nb][0] = s_loc[nb][1] = 0.f; q_loc[nb][0] = q_loc[nb][1] = 0.f; }

    {
        int row0 = mbase + wm * 16 + (lane >> 2);
        #pragma unroll
        for (int nb = 0; nb < 4; nb++) {
            int col = nbase + wn * 32 + nb * 8 + (lane & 3) * 2;
            float f[4];
            #pragma unroll
            for (int i = 0; i < 4; i++)
                f[i] = fmaf((float)d[2][nb][i], 65536.f,
                            fmaf((float)d[1][nb][i], 256.f,
                                 (float)d[0][nb][i])) * (1.f / 1048576.f);
            stcs2(g_h + (size_t)row0 * H_DIM + col,       make_float2(f[0], f[1]));
            stcs2(g_h + (size_t)(row0 + 8) * H_DIM + col, make_float2(f[2], f[3]));
            s_loc[nb][0] += f[0] + f[2];            q_loc[nb][0] += f[0] * f[0] + f[2] * f[2];
            s_loc[nb][1] += f[1] + f[3];            q_loc[nb][1] += f[1] * f[1] + f[3] * f[3];
        }
    }
    #pragma unroll
    for (int nb = 0; nb < 4; nb++)
        #pragma unroll
        for (int p = 0; p < 2; p++) {
            #pragma unroll
            for (int off = 4; off <= 16; off <<= 1) {
                s_loc[nb][p] += __shfl_xor_sync(0xFFFFFFFFu, s_loc[nb][p], off);
                q_loc[nb][p] += __shfl_xor_sync(0xFFFFFFFFu, q_loc[nb][p], off);
            }
        }
    __syncthreads();
    float* sm_s = (float*)smem;          // [4][128]
    float* sm_q = sm_s + 512;            // [4][128]
    if (lane < 4) {
        #pragma unroll
        for (int nb = 0; nb < 4; nb++)
            #pragma unroll
            for (int p = 0; p < 2; p++) {
                int idx = wn * 32 + nb * 8 + lane * 2 + p;
                sm_s[wm * 128 + idx] = s_loc[nb][p];
                sm_q[wm * 128 + idx] = q_loc[nb][p];
            }
    }
    __syncthreads();
    if (tid < 128) {
        float s = ((sm_s[tid] + sm_s[128 + tid]) + sm_s[256 + tid]) + sm_s[384 + tid];
        float q = ((sm_q[tid] + sm_q[128 + tid]) + sm_q[256 + tid]) + sm_q[384 + tid];
        size_t gidx = (size_t)blockIdx.y * H_DIM + nbase + tid;
        g_psum[gidx] = s;
        g_psq [gidx] = q;
    }
}

// ---------------- stats finalize: reduce 256 mtile partials ----------------
__global__ void __launch_bounds__(256) k_stats_fin(const float* __restrict__ gamma,
                                                   const float* __restrict__ beta) {
    int j = blockIdx.x * 256 + threadIdx.x;
    float s = 0.f, q = 0.f;
    for (int p = 0; p < MTILES; p++) {
        s += g_psum[(size_t)p * H_DIM + j];
        q += g_psq [(size_t)p * H_DIM + j];
    }
    float mean = s * (1.f / B_DIM);
    float var  = q * (1.f / B_DIM) - mean * mean;
    float a = gamma[j] * rsqrtf(var + 1e-5f);
    float t; unsigned neg;
    if (a != 0.f) { t = mean - beta[j] / a; neg = (a < 0.f) ? 1u : 0u; }
    else { t = (beta[j] > 0.f) ? -__int_as_float(0x7f800000) : __int_as_float(0x7f800000); neg = 0u; }
    g_thr[j] = t;
    unsigned word = __ballot_sync(0xFFFFFFFFu, neg);
    if ((threadIdx.x & 31) == 0) g_negw[j >> 5] = word;
}

// ---------------- fused sign / XOR-popcount GEMM2 / log-softmax ----------------
// Batched loads (MLP=32) before any ballot: removes the load->ballot serial chain.
__global__ void __launch_bounds__(256) k_final(float* __restrict__ out) {
    __shared__ unsigned hw[2][128];
    __shared__ int wsum[2][4][OUT_DIM];
    int g = threadIdx.x >> 7;                 // row-group 0/1
    int tid = threadIdx.x & 127;
    int row = blockIdx.x * 2 + g;
    int lane = tid & 31, w = tid >> 5;
    const float* hr = g_h + (size_t)row * H_DIM;

    // phase 1: 32 independent coalesced loads per thread
    float v[32];
    #pragma unroll
    for (int i = 0; i < 32; i++) {
        int col = (w + i * 4) * 32 + lane;
        v[i] = __ldcs(hr + col);
    }
    // phase 2: compare + ballot from registers (thr is L1-resident broadcast)
    #pragma unroll
    for (int i = 0; i < 32; i++) {
        int c = w + i * 4;
        int col = c * 32 + lane;
        unsigned bit = (v[i] > g_thr[col]) ? 1u : 0u;
        unsigned word = __ballot_sync(0xFFFFFFFFu, bit);
        if (lane == 0) hw[g][c] = word ^ g_negw[c];
    }
    __syncthreads();
    unsigned mw = hw[g][tid];
    #pragma unroll
    for (int o = 0; o < OUT_DIM; o++) {
        int s = __popc(mw ^ g_w2b[o * 128 + tid]);
        s = (int)__reduce_add_sync(0xFFFFFFFFu, (unsigned)s);
        if (lane == 0) wsum[g][w][o] = s;
    }
    __syncthreads();
    if (tid == 0) {
        float lg[OUT_DIM], mx = -3.4e38f;
        #pragma unroll
        for (int o = 0; o < OUT_DIM; o++) {
            int mis = wsum[g][0][o] + wsum[g][1][o] + wsum[g][2][o] + wsum[g][3][o];
            lg[o] = (float)(H_DIM - 2 * mis);
            mx = fmaxf(mx, lg[o]);
        }
        float se = 0.f;
        #pragma unroll
        for (int o = 0; o < OUT_DIM; o++) se += expf(lg[o] - mx);
        float lse = mx + logf(se);
        #pragma unroll
        for (int o = 0; o < OUT_DIM; o++) out[(size_t)row * OUT_DIM + o] = lg[o] - lse;
    }
}

// ---------------- launch ----------------
extern "C" void kernel_launch(void* const* d_in, const int* in_sizes, int n_in,
                              void* d_out, int out_size) {
    (void)in_sizes; (void)n_in; (void)out_size;
    const float* x     = (const float*)d_in[0];
    const float* W1    = (const float*)d_in[1];
    const float* gamma = (const float*)d_in[2];
    const float* beta  = (const float*)d_in[3];
    const float* W2    = (const float*)d_in[4];

    cudaFuncSetAttribute(k_gemm1, cudaFuncAttributeMaxDynamicSharedMemorySize, SMEM_TOTAL);

    k_prep<<<(unsigned)((PREP_TOTAL + 255) / 256), 256>>>(x, W1, W2);

    k_gemm1<<<dim3(H_DIM / NT, B_DIM / MT), 512, SMEM_TOTAL>>>();

    k_stats_fin<<<H_DIM / 256, 256>>>(gamma, beta);

    k_final<<<B_DIM / 2, 256>>>((float*)d_out);
}